// round 1
// baseline (speedup 1.0000x reference)
#include <cuda_runtime.h>

#define BATCH   8
#define NNODE   256
#define XHIN    9
#define XHHID   64
#define POSHID  192
#define MFREQ   64
#define TWO_PI_F 6.283185307179586f

// scratch (no allocations allowed)
__device__ float g_xc[BATCH * NNODE * 3];
__device__ float g_Nsum[BATCH];

// ---------------------------------------------------------------------------
// Kernel 1: per-batch masked mean removal of x, then [x_c, h] @ W_xh + b_xh
// writes out[b, n, 0:64], stores centered x and N to globals for kernel 2.
// grid = 8, block = 256
// ---------------------------------------------------------------------------
__global__ __launch_bounds__(256) void k1_center_emb(
    const float* __restrict__ xh,
    const float* __restrict__ node_mask,
    const float* __restrict__ W_xh,
    const float* __restrict__ b_xh,
    float* __restrict__ out)
{
    int b = blockIdx.x;
    int n = threadIdx.x;
    int row = b * NNODE + n;

    float m  = node_mask[row];
    float x0 = xh[row * XHIN + 0];
    float x1 = xh[row * XHIN + 1];
    float x2 = xh[row * XHIN + 2];

    __shared__ float red[NNODE][4];
    __shared__ float sW[XHIN * XHHID];
    __shared__ float sB[XHHID];

    red[n][0] = x0 * m;
    red[n][1] = x1 * m;
    red[n][2] = x2 * m;
    red[n][3] = m;

    // stage weights while reduction syncs happen
    for (int i = n; i < XHIN * XHHID; i += 256) sW[i] = W_xh[i];
    if (n < XHHID) sB[n] = b_xh[n];
    __syncthreads();

    #pragma unroll
    for (int s = 128; s > 0; s >>= 1) {
        if (n < s) {
            red[n][0] += red[n + s][0];
            red[n][1] += red[n + s][1];
            red[n][2] += red[n + s][2];
            red[n][3] += red[n + s][3];
        }
        __syncthreads();
    }

    float Ns   = red[0][3];
    float invN = 1.0f / Ns;
    float mean0 = red[0][0] * invN;
    float mean1 = red[0][1] * invN;
    float mean2 = red[0][2] * invN;

    float xc0 = (x0 - mean0) * m;
    float xc1 = (x1 - mean1) * m;
    float xc2 = (x2 - mean2) * m;

    g_xc[row * 3 + 0] = xc0;
    g_xc[row * 3 + 1] = xc1;
    g_xc[row * 3 + 2] = xc2;
    if (n == 0) g_Nsum[b] = Ns;

    float h0 = xh[row * XHIN + 3];
    float h1 = xh[row * XHIN + 4];
    float h2 = xh[row * XHIN + 5];
    float h3 = xh[row * XHIN + 6];
    float h4 = xh[row * XHIN + 7];
    float h5 = xh[row * XHIN + 8];

    float* orow = out + (size_t)row * 256;
    #pragma unroll 4
    for (int o = 0; o < XHHID; o++) {
        float acc = sB[o];
        acc = fmaf(xc0, sW[0 * XHHID + o], acc);
        acc = fmaf(xc1, sW[1 * XHHID + o], acc);
        acc = fmaf(xc2, sW[2 * XHHID + o], acc);
        acc = fmaf(h0,  sW[3 * XHHID + o], acc);
        acc = fmaf(h1,  sW[4 * XHHID + o], acc);
        acc = fmaf(h2,  sW[5 * XHHID + o], acc);
        acc = fmaf(h3,  sW[6 * XHHID + o], acc);
        acc = fmaf(h4,  sW[7 * XHHID + o], acc);
        acc = fmaf(h5,  sW[8 * XHHID + o], acc);
        orow[o] = acc * m;
    }
}

// ---------------------------------------------------------------------------
// Kernel 2: positional-encoding sum + fused 128->192 projection.
// Each block handles 2 rows (b, i0), (b, i0+1).
//   Phase B: 2*256 distances -> a = 2*pi*d in smem (matches reference rounding)
//   Phase C: 8 warps = 2 rows x 4 j-quarters; lane l owns freqs l and l+32;
//            accumulates masked sin/cos sums (4 MUFU + 4 FMA per j)
//   Phase E: combine partials, scale by mask_i/N, matvec with W_pos, write out.
// grid = 1024, block = 256
// ---------------------------------------------------------------------------
__global__ __launch_bounds__(256) void k2_pe(
    const float* __restrict__ node_mask,
    const float* __restrict__ W_pos,
    const float* __restrict__ b_pos,
    float* __restrict__ out)
{
    int b  = blockIdx.x >> 7;
    int i0 = (blockIdx.x & 127) << 1;
    int t  = threadIdx.x;

    __shared__ float a_sm[2][NNODE];
    __shared__ float mk[NNODE];
    __shared__ float Sp[2][4][128];
    __shared__ float S_sm[2][128];
    __shared__ float sc[2];   // [0] = 1/N, [1] = 256/N

    mk[t] = node_mask[b * NNODE + t];
    if (t == 0) {
        float Ns = g_Nsum[b];
        sc[0] = 1.0f / Ns;
        sc[1] = 256.0f / Ns;
    }
    __syncthreads();

    // Phase B: angles-per-unit-freq: a = fl(2*pi*d), same rounding as reference
    #pragma unroll
    for (int it = 0; it < 2; it++) {
        int p = t + it * 256;
        int r = p >> 8, j = p & 255;
        int gi = (b * NNODE + i0 + r) * 3;
        int gj = (b * NNODE + j) * 3;
        float dx = g_xc[gi + 0] - g_xc[gj + 0];
        float dy = g_xc[gi + 1] - g_xc[gj + 1];
        float dz = g_xc[gi + 2] - g_xc[gj + 2];
        float sq = fmaxf(fmaf(dx, dx, fmaf(dy, dy, dz * dz)), 0.0f);
        a_sm[r][j] = TWO_PI_F * sqrtf(sq + 1e-12f);
    }
    __syncthreads();

    // Phase C
    int w = t >> 5, l = t & 31;
    int r = w >> 2, q = w & 3;
    const float c1 = 0.10381025296522944f;   // log2(100)/64
    float f1 = exp2f((float)l * c1);
    float f2 = exp2f((float)(l + 32) * c1);

    float ss1 = 0.f, ss2 = 0.f, cc1 = 0.f, cc2 = 0.f;
    int j0 = q << 6;
    #pragma unroll 8
    for (int jj = 0; jj < 64; jj++) {
        float a  = a_sm[r][j0 + jj];
        float mj = mk[j0 + jj];
        float an1 = a * f1;
        float an2 = a * f2;
        float s1 = __sinf(an1), cv1 = __cosf(an1);
        float s2 = __sinf(an2), cv2 = __cosf(an2);
        ss1 = fmaf(mj, s1,  ss1);
        cc1 = fmaf(mj, cv1, cc1);
        ss2 = fmaf(mj, s2,  ss2);
        cc2 = fmaf(mj, cv2, cc2);
    }

    // pe layout: [sin(k=0..63), cos(k=0..63)]
    Sp[r][q][l]      = ss1;
    Sp[r][q][l + 32] = ss2;
    Sp[r][q][64 + l] = cc1;
    Sp[r][q][96 + l] = cc2;
    __syncthreads();

    // Phase E1: combine 4 quarter-partials, fold mask_i and 1/N
    {
        int rr = t >> 7, k = t & 127;
        float s = Sp[rr][0][k] + Sp[rr][1][k] + Sp[rr][2][k] + Sp[rr][3][k];
        S_sm[rr][k] = s * mk[i0 + rr] * sc[0];
    }
    __syncthreads();

    // Phase E2: matvec S(2x128) @ W_pos(128x192) + bias, final mask
    if (t < POSHID) {
        int c = t;
        float acc0 = 0.f, acc1 = 0.f;
        #pragma unroll 8
        for (int k = 0; k < 128; k++) {
            float wv = W_pos[k * POSHID + c];
            acc0 = fmaf(S_sm[0][k], wv, acc0);
            acc1 = fmaf(S_sm[1][k], wv, acc1);
        }
        float bp = b_pos[c] * sc[1];
        float m0 = mk[i0], m1 = mk[i0 + 1];
        size_t base = ((size_t)(b * NNODE + i0)) * 256 + 64;
        out[base + c]       = (acc0 + bp) * m0;
        out[base + 256 + c] = (acc1 + bp) * m1;
    }
}

extern "C" void kernel_launch(void* const* d_in, const int* in_sizes, int n_in,
                              void* d_out, int out_size)
{
    // inputs (metadata order): t, xh, node_mask, edge_mask, W_xh, b_xh, W_pos, b_pos
    const float* xh        = (const float*)d_in[1];
    const float* node_mask = (const float*)d_in[2];
    const float* W_xh      = (const float*)d_in[4];
    const float* b_xh      = (const float*)d_in[5];
    const float* W_pos     = (const float*)d_in[6];
    const float* b_pos     = (const float*)d_in[7];
    float* out = (float*)d_out;

    k1_center_emb<<<BATCH, 256>>>(xh, node_mask, W_xh, b_xh, out);
    k2_pe<<<BATCH * (NNODE / 2), 256>>>(node_mask, W_pos, b_pos, out);
}

// round 2
// speedup vs baseline: 1.3957x; 1.3957x over previous
#include <cuda_runtime.h>

#define BATCH   8
#define NNODE   256
#define XHIN    9
#define XHHID   64
#define POSHID  192
#define TWO_PI_F 6.283185307179586f

// ---------------------------------------------------------------------------
// Single fused kernel. Each block handles batch b, rows (i0, i0+1).
//   1. Load mask + x(3) for all 256 nodes of batch b into smem.
//   2. Block-reduce masked mean + N (shuffles + 2 barriers).
//   3. Center x in smem: xc = (x - mean)*m  (matches reference rounding).
//   4. Phase B: 2x256 angles a = 2*pi*d packed with mask into float2 smem.
//   5. Phase C: 8 warps = 2 rows x 4 j-quarters; lane l owns freqs l, l+32;
//      masked sin/cos accumulation (4 MUFU + 4 FMA per j) — the MUFU floor.
//   6. E1: combine quarter partials, fold mask_i/N.
//   7. E2: S(2x128) @ W_pos(128x192) + bias -> out[:,64:256];
//      plus the 9->64 xh embedding for the 2 rows -> out[:,0:64].
// grid = 1024, block = 256
// ---------------------------------------------------------------------------
__global__ __launch_bounds__(256) void fused_ditemb(
    const float* __restrict__ xh,
    const float* __restrict__ node_mask,
    const float* __restrict__ W_xh,
    const float* __restrict__ b_xh,
    const float* __restrict__ W_pos,
    const float* __restrict__ b_pos,
    float* __restrict__ out)
{
    int b  = blockIdx.x >> 7;
    int i0 = (blockIdx.x & 127) << 1;
    int t  = threadIdx.x;
    int w  = t >> 5, l = t & 31;

    __shared__ float  xs[3][NNODE];
    __shared__ float  mk[NNODE];
    __shared__ float2 am[2][NNODE];
    __shared__ float  Sp[2][4][128];
    __shared__ float  S_sm[2][128];
    __shared__ float  wred[8][4];
    __shared__ float  mean_s[3];
    __shared__ float  sc[2];          // [0]=1/N, [1]=256/N
    __shared__ float  sW[XHIN * XHHID];
    __shared__ float  sB[XHHID];

    // -- 1: loads + per-warp partial reduction -----------------------------
    int row = b * NNODE + t;
    float m  = node_mask[row];
    float x0 = xh[row * XHIN + 0];
    float x1 = xh[row * XHIN + 1];
    float x2 = xh[row * XHIN + 2];
    mk[t] = m;

    float p0 = x0 * m, p1 = x1 * m, p2 = x2 * m, p3 = m;
    #pragma unroll
    for (int off = 16; off > 0; off >>= 1) {
        p0 += __shfl_down_sync(0xffffffffu, p0, off);
        p1 += __shfl_down_sync(0xffffffffu, p1, off);
        p2 += __shfl_down_sync(0xffffffffu, p2, off);
        p3 += __shfl_down_sync(0xffffffffu, p3, off);
    }
    if (l == 0) { wred[w][0] = p0; wred[w][1] = p1; wred[w][2] = p2; wred[w][3] = p3; }

    // stage embedding weights while reduction syncs happen
    for (int i = t; i < XHIN * XHHID; i += 256) sW[i] = W_xh[i];
    if (t < XHHID) sB[t] = b_xh[t];
    __syncthreads();                                   // 1

    // -- 2: finalize mean / N ---------------------------------------------
    if (t < 4) {
        float s = wred[0][t] + wred[1][t] + wred[2][t] + wred[3][t]
                + wred[4][t] + wred[5][t] + wred[6][t] + wred[7][t];
        wred[0][t] = s;
    }
    __syncthreads();                                   // 2
    if (t < 3) mean_s[t] = wred[0][t] / wred[0][3];
    if (t == 0) {
        float Ns = wred[0][3];
        sc[0] = 1.0f / Ns;
        sc[1] = 256.0f / Ns;
    }
    __syncthreads();                                   // 3

    // -- 3: center x in smem (reference arithmetic) ------------------------
    xs[0][t] = (x0 - mean_s[0]) * m;
    xs[1][t] = (x1 - mean_s[1]) * m;
    xs[2][t] = (x2 - mean_s[2]) * m;
    __syncthreads();                                   // 4

    // -- 4: Phase B — angles (2 rows x 256 cols) ---------------------------
    #pragma unroll
    for (int it = 0; it < 2; it++) {
        int p = t + it * 256;
        int r = p >> 8, j = p & 255;
        float dx = xs[0][i0 + r] - xs[0][j];
        float dy = xs[1][i0 + r] - xs[1][j];
        float dz = xs[2][i0 + r] - xs[2][j];
        float sq = fmaxf(fmaf(dx, dx, fmaf(dy, dy, dz * dz)), 0.0f);
        float2 v;
        v.x = TWO_PI_F * sqrtf(sq + 1e-12f);
        v.y = mk[j];
        am[r][j] = v;
    }
    __syncthreads();                                   // 5

    // -- 5: Phase C — MUFU sin/cos accumulation ----------------------------
    int r = w >> 2, q = w & 3;
    const float c1 = 0.10381025296522944f;             // log2(100)/64
    float f1 = exp2f((float)l * c1);
    float f2 = exp2f((float)(l + 32) * c1);

    float ss1 = 0.f, ss2 = 0.f, cc1 = 0.f, cc2 = 0.f;
    int j0 = q << 6;
    #pragma unroll 16
    for (int jj = 0; jj < 64; jj++) {
        float2 v = am[r][j0 + jj];
        float an1 = v.x * f1;
        float an2 = v.x * f2;
        float s1 = __sinf(an1), cv1 = __cosf(an1);
        float s2 = __sinf(an2), cv2 = __cosf(an2);
        ss1 = fmaf(v.y, s1,  ss1);
        cc1 = fmaf(v.y, cv1, cc1);
        ss2 = fmaf(v.y, s2,  ss2);
        cc2 = fmaf(v.y, cv2, cc2);
    }

    Sp[r][q][l]      = ss1;
    Sp[r][q][l + 32] = ss2;
    Sp[r][q][64 + l] = cc1;
    Sp[r][q][96 + l] = cc2;
    __syncthreads();                                   // 6

    // -- 6: E1 — combine partials, fold mask_i / N -------------------------
    {
        int rr = t >> 7, k = t & 127;
        float s = Sp[rr][0][k] + Sp[rr][1][k] + Sp[rr][2][k] + Sp[rr][3][k];
        S_sm[rr][k] = s * mk[i0 + rr] * sc[0];
    }
    __syncthreads();                                   // 7

    // -- 7: E2 — PE projection (192 threads) -------------------------------
    if (t < POSHID) {
        int c = t;
        float acc0 = 0.f, acc1 = 0.f;
        #pragma unroll 8
        for (int k = 0; k < 128; k++) {
            float wv = W_pos[k * POSHID + c];
            acc0 = fmaf(S_sm[0][k], wv, acc0);
            acc1 = fmaf(S_sm[1][k], wv, acc1);
        }
        float bp = b_pos[c] * sc[1];
        float m0 = mk[i0], m1 = mk[i0 + 1];
        size_t base = ((size_t)(b * NNODE + i0)) * 256 + 64;
        out[base + c]       = (acc0 + bp) * m0;
        out[base + 256 + c] = (acc1 + bp) * m1;
    }

    // -- 8: xh embedding for the 2 rows (128 threads) ----------------------
    if (t < 2 * XHHID) {
        int rr = t >> 6, o = t & 63;
        int grow = b * NNODE + i0 + rr;
        float mr  = mk[i0 + rr];
        float xc0 = xs[0][i0 + rr];
        float xc1 = xs[1][i0 + rr];
        float xc2 = xs[2][i0 + rr];
        const float* hrow = xh + (size_t)grow * XHIN + 3;
        float h0 = hrow[0], h1 = hrow[1], h2 = hrow[2];
        float h3 = hrow[3], h4 = hrow[4], h5 = hrow[5];

        float acc = sB[o];
        acc = fmaf(xc0, sW[0 * XHHID + o], acc);
        acc = fmaf(xc1, sW[1 * XHHID + o], acc);
        acc = fmaf(xc2, sW[2 * XHHID + o], acc);
        acc = fmaf(h0,  sW[3 * XHHID + o], acc);
        acc = fmaf(h1,  sW[4 * XHHID + o], acc);
        acc = fmaf(h2,  sW[5 * XHHID + o], acc);
        acc = fmaf(h3,  sW[6 * XHHID + o], acc);
        acc = fmaf(h4,  sW[7 * XHHID + o], acc);
        acc = fmaf(h5,  sW[8 * XHHID + o], acc);
        out[(size_t)grow * 256 + o] = acc * mr;
    }
}

extern "C" void kernel_launch(void* const* d_in, const int* in_sizes, int n_in,
                              void* d_out, int out_size)
{
    // inputs (metadata order): t, xh, node_mask, edge_mask, W_xh, b_xh, W_pos, b_pos
    const float* xh        = (const float*)d_in[1];
    const float* node_mask = (const float*)d_in[2];
    const float* W_xh      = (const float*)d_in[4];
    const float* b_xh      = (const float*)d_in[5];
    const float* W_pos     = (const float*)d_in[6];
    const float* b_pos     = (const float*)d_in[7];
    float* out = (float*)d_out;

    fused_ditemb<<<BATCH * (NNODE / 2), 256>>>(xh, node_mask, W_xh, b_xh,
                                               W_pos, b_pos, out);
}

// round 3
// speedup vs baseline: 1.4136x; 1.0128x over previous
#include <cuda_runtime.h>

#define BATCH   8
#define NNODE   256
#define XHIN    9
#define XHHID   64
#define POSHID  192
#define TWO_PI_F 6.283185307179586f
#define NTILE   8      // 256 / 32
#define NPAIR   36     // NTILE*(NTILE+1)/2

// Partial PE sums: [batch][slot][row][freq], freq = [sin 0..63, cos 64..127].
// Row in row-tile T gets j-side partials in slots 0..T-1 (from pairs (ti,T))
// and i-side partials in slots T..7 (from pairs (T,tj)) -> all 8 slots covered
// exactly once => no atomics, no zero-init needed.
__device__ float g_Spart[BATCH][NTILE][NNODE][128];

// ---------------------------------------------------------------------------
// Pair kernel: one block per (batch, upper-triangular 32x32 tile-pair).
// Off-diagonal tiles compute each pair ONCE and contribute to both row sums
// (i-side in registers, j-side via smem staging) -> 0.5625x MUFU vs full.
// grid = 288, block = 256 (8 warps: g = freq-half, r = 8-row group)
// ---------------------------------------------------------------------------
__global__ __launch_bounds__(256) void pair_kernel(
    const float* __restrict__ xh,
    const float* __restrict__ node_mask)
{
    int b = blockIdx.x / NPAIR;
    int p = blockIdx.x % NPAIR;
    int ti = 0, rem = p;
    while (rem >= NTILE - ti) { rem -= NTILE - ti; ti++; }
    int tj = ti + rem;
    bool offdiag = (ti != tj);

    int t = threadIdx.x;
    int w = t >> 5, l = t & 31;
    int r = w & 3;      // row group: i-rows r*8 .. r*8+7 (tile-local)
    int g = w >> 2;     // freq half: freqs g*32 + l

    __shared__ float  xi[3][32], xj[3][32];
    __shared__ float  mi_sm[32], mj_sm[32];
    __shared__ float  a_sm[32 * 32];      // [j][i] : 2*pi*d
    __shared__ float2 SjP[8][16][32];     // [warp][j-in-half][lane] -> 32 KB

    // -- load raw x + masks for both tiles (mean cancels in distances) ------
    if (t < 32) {
        int rowg = b * NNODE + ti * 32 + t;
        xi[0][t] = xh[rowg * XHIN + 0];
        xi[1][t] = xh[rowg * XHIN + 1];
        xi[2][t] = xh[rowg * XHIN + 2];
        mi_sm[t] = node_mask[rowg];
    } else if (t < 64) {
        int tt = t - 32;
        int rowg = b * NNODE + tj * 32 + tt;
        xj[0][tt] = xh[rowg * XHIN + 0];
        xj[1][tt] = xh[rowg * XHIN + 1];
        xj[2][tt] = xh[rowg * XHIN + 2];
        mj_sm[tt] = node_mask[rowg];
    }
    __syncthreads();

    // -- angles a = 2*pi*d for the whole 32x32 tile -------------------------
    #pragma unroll
    for (int k = 0; k < 4; k++) {
        int q = t + k * 256;
        int i = q & 31, j = q >> 5;
        float dx = xi[0][i] - xj[0][j];
        float dy = xi[1][i] - xj[1][j];
        float dz = xi[2][i] - xj[2][j];
        float sq = fmaxf(fmaf(dx, dx, fmaf(dy, dy, dz * dz)), 0.0f);
        a_sm[j * 32 + i] = TWO_PI_F * sqrtf(sq + 1e-12f);
    }
    __syncthreads();

    const float c1 = 0.10381025296522944f;           // log2(100)/64
    float f = exp2f((float)(g * 32 + l) * c1);

    float mi[8];
    #pragma unroll
    for (int k = 0; k < 8; k++) mi[k] = mi_sm[r * 8 + k];

    float ssA[8], ccA[8];
    #pragma unroll
    for (int k = 0; k < 8; k++) { ssA[k] = 0.f; ccA[k] = 0.f; }

    // -- main loop: 2 halves of 16 j each, staged j-side flush --------------
    for (int h = 0; h < 2; h++) {
        #pragma unroll 4
        for (int j2 = 0; j2 < 16; j2++) {
            int j = h * 16 + j2;
            float mj = mj_sm[j];
            const float4* ap = (const float4*)&a_sm[j * 32 + r * 8];
            float4 a0 = ap[0];
            float4 a1 = ap[1];
            float av[8] = {a0.x, a0.y, a0.z, a0.w, a1.x, a1.y, a1.z, a1.w};
            float sjs = 0.f, sjc = 0.f;
            #pragma unroll
            for (int k = 0; k < 8; k++) {
                float ang = av[k] * f;
                float s = __sinf(ang);
                float c = __cosf(ang);
                ssA[k] = fmaf(mj, s, ssA[k]);       // i-side: += m_j * sin
                ccA[k] = fmaf(mj, c, ccA[k]);
                sjs    = fmaf(mi[k], s, sjs);       // j-side: += m_i * sin
                sjc    = fmaf(mi[k], c, sjc);
            }
            if (offdiag) SjP[w][j2][l] = make_float2(sjs, sjc);
        }

        if (offdiag) {
            __syncthreads();
            // reduce 4 row-group warps per freq-half, write j-side partials
            #pragma unroll
            for (int k = 0; k < 4; k++) {
                int idx = t + k * 256;               // 0..1023
                int gg  = idx >> 9;                  // freq half
                int jj  = (idx >> 5) & 15;           // j within half
                int ll  = idx & 31;                  // lane/freq
                float2 v0 = SjP[gg * 4 + 0][jj][ll];
                float2 v1 = SjP[gg * 4 + 1][jj][ll];
                float2 v2 = SjP[gg * 4 + 2][jj][ll];
                float2 v3 = SjP[gg * 4 + 3][jj][ll];
                float ss = (v0.x + v1.x) + (v2.x + v3.x);
                float cc = (v0.y + v1.y) + (v2.y + v3.y);
                float* rp = &g_Spart[b][ti][tj * 32 + h * 16 + jj][0];
                rp[gg * 32 + ll]      = ss;
                rp[64 + gg * 32 + ll] = cc;
            }
            __syncthreads();
        }
    }

    // -- i-side flush -------------------------------------------------------
    float* basei = &g_Spart[b][tj][ti * 32][0];
    #pragma unroll
    for (int k = 0; k < 8; k++) {
        float* rp = basei + (r * 8 + k) * 128;
        rp[g * 32 + l]      = ssA[k];
        rp[64 + g * 32 + l] = ccA[k];
    }
}

// ---------------------------------------------------------------------------
// Epilogue: per (batch, 2 rows): sum the 8 slot partials, fold mask_i/N,
// project 128->192 with W_pos + bias, plus the 9->64 xh embedding (needs the
// masked mean -> recomputed per block with a shuffle reduction).
// grid = 1024, block = 256
// ---------------------------------------------------------------------------
__global__ __launch_bounds__(256) void ep_ditemb(
    const float* __restrict__ xh,
    const float* __restrict__ node_mask,
    const float* __restrict__ W_xh,
    const float* __restrict__ b_xh,
    const float* __restrict__ W_pos,
    const float* __restrict__ b_pos,
    float* __restrict__ out)
{
    int b  = blockIdx.x >> 7;
    int i0 = (blockIdx.x & 127) << 1;
    int t  = threadIdx.x;
    int w  = t >> 5, l = t & 31;

    __shared__ float mk[NNODE];
    __shared__ float S_sm[2][128];
    __shared__ float wred[8][4];
    __shared__ float mean_s[3];
    __shared__ float sc[2];            // [0]=1/N, [1]=256/N
    __shared__ float xc2[2][3];        // centered x for the 2 rows
    __shared__ float sW[XHIN * XHHID];
    __shared__ float sB[XHHID];

    // -- slot-sum loads issued early (long latency, L2-hot) -----------------
    int rr = t >> 7, ff = t & 127;
    float ssum = 0.f;
    #pragma unroll
    for (int slot = 0; slot < NTILE; slot++)
        ssum += g_Spart[b][slot][i0 + rr][ff];

    // -- masked mean / N reduction ------------------------------------------
    int row = b * NNODE + t;
    float m  = node_mask[row];
    float x0 = xh[row * XHIN + 0];
    float x1 = xh[row * XHIN + 1];
    float x2 = xh[row * XHIN + 2];
    mk[t] = m;

    float p0 = x0 * m, p1 = x1 * m, p2 = x2 * m, p3 = m;
    #pragma unroll
    for (int off = 16; off > 0; off >>= 1) {
        p0 += __shfl_down_sync(0xffffffffu, p0, off);
        p1 += __shfl_down_sync(0xffffffffu, p1, off);
        p2 += __shfl_down_sync(0xffffffffu, p2, off);
        p3 += __shfl_down_sync(0xffffffffu, p3, off);
    }
    if (l == 0) { wred[w][0] = p0; wred[w][1] = p1; wred[w][2] = p2; wred[w][3] = p3; }

    for (int i = t; i < XHIN * XHHID; i += 256) sW[i] = W_xh[i];
    if (t < XHHID) sB[t] = b_xh[t];
    __syncthreads();

    if (t < 4) {
        float s = wred[0][t] + wred[1][t] + wred[2][t] + wred[3][t]
                + wred[4][t] + wred[5][t] + wred[6][t] + wred[7][t];
        wred[0][t] = s;
    }
    __syncthreads();
    if (t < 3) mean_s[t] = wred[0][t] / wred[0][3];
    if (t == 0) {
        float Ns = wred[0][3];
        sc[0] = 1.0f / Ns;
        sc[1] = 256.0f / Ns;
    }
    __syncthreads();

    // centered x for the block's 2 rows (reference arithmetic)
    if (t == i0 || t == i0 + 1) {
        int k = t - i0;
        xc2[k][0] = (x0 - mean_s[0]) * m;
        xc2[k][1] = (x1 - mean_s[1]) * m;
        xc2[k][2] = (x2 - mean_s[2]) * m;
    }

    // finalize S = (slot sum) * mask_i / N
    S_sm[rr][ff] = ssum * mk[i0 + rr] * sc[0];
    __syncthreads();

    // -- PE projection: S(2x128) @ W_pos(128x192) + bias --------------------
    if (t < POSHID) {
        int c = t;
        float acc0 = 0.f, acc1 = 0.f;
        #pragma unroll 8
        for (int k = 0; k < 128; k++) {
            float wv = W_pos[k * POSHID + c];
            acc0 = fmaf(S_sm[0][k], wv, acc0);
            acc1 = fmaf(S_sm[1][k], wv, acc1);
        }
        float bp = b_pos[c] * sc[1];
        float m0 = mk[i0], m1 = mk[i0 + 1];
        size_t base = ((size_t)(b * NNODE + i0)) * 256 + 64;
        out[base + c]       = (acc0 + bp) * m0;
        out[base + 256 + c] = (acc1 + bp) * m1;
    }

    // -- xh embedding for the 2 rows ----------------------------------------
    if (t < 2 * XHHID) {
        int k = t >> 6, o = t & 63;
        int grow = b * NNODE + i0 + k;
        float mr = mk[i0 + k];
        const float* hrow = xh + (size_t)grow * XHIN + 3;
        float h0 = hrow[0], h1 = hrow[1], h2 = hrow[2];
        float h3 = hrow[3], h4 = hrow[4], h5 = hrow[5];

        float acc = sB[o];
        acc = fmaf(xc2[k][0], sW[0 * XHHID + o], acc);
        acc = fmaf(xc2[k][1], sW[1 * XHHID + o], acc);
        acc = fmaf(xc2[k][2], sW[2 * XHHID + o], acc);
        acc = fmaf(h0, sW[3 * XHHID + o], acc);
        acc = fmaf(h1, sW[4 * XHHID + o], acc);
        acc = fmaf(h2, sW[5 * XHHID + o], acc);
        acc = fmaf(h3, sW[6 * XHHID + o], acc);
        acc = fmaf(h4, sW[7 * XHHID + o], acc);
        acc = fmaf(h5, sW[8 * XHHID + o], acc);
        out[(size_t)grow * 256 + o] = acc * mr;
    }
}

extern "C" void kernel_launch(void* const* d_in, const int* in_sizes, int n_in,
                              void* d_out, int out_size)
{
    // inputs (metadata order): t, xh, node_mask, edge_mask, W_xh, b_xh, W_pos, b_pos
    const float* xh        = (const float*)d_in[1];
    const float* node_mask = (const float*)d_in[2];
    const float* W_xh      = (const float*)d_in[4];
    const float* b_xh      = (const float*)d_in[5];
    const float* W_pos     = (const float*)d_in[6];
    const float* b_pos     = (const float*)d_in[7];
    float* out = (float*)d_out;

    pair_kernel<<<BATCH * NPAIR, 256>>>(xh, node_mask);
    ep_ditemb<<<BATCH * (NNODE / 2), 256>>>(xh, node_mask, W_xh, b_xh,
                                            W_pos, b_pos, out);
}